// round 4
// baseline (speedup 1.0000x reference)
#include <cuda_runtime.h>

namespace {
constexpr int N_COLS = 8192;
constexpr int W_MAX  = 15;     // widths w = 2..15
constexpr int NW     = 14;
constexpr int HALO   = 14;     // W_MAX - 1
constexpr int TPB    = 256;
constexpr int K_TOK  = 8;      // tokens per thread
constexpr int TILE   = TPB * K_TOK;        // 2048
constexpr int LPAD   = 16;                 // left pad (>= HALO, 16-aligned)
constexpr int SV_PAD = 2080;               // TILE + LPAD + HALO rounded /4
constexpr float NEGV = -1.0e9f;
constexpr unsigned KEY_NINF = 0x007fffffu; // fkey(-inf)
}

// order-preserving float<->uint key (total order incl. -inf)
__device__ __forceinline__ unsigned fkey(float f) {
    int u = __float_as_int(f);
    return (u >= 0) ? ((unsigned)u | 0x80000000u) : ~(unsigned)u;
}
__device__ __forceinline__ float funkey(unsigned k) {
    unsigned u = (k & 0x80000000u) ? (k & 0x7fffffffu) : ~k;
    return __int_as_float((int)u);
}

__global__ __launch_bounds__(TPB, 4) void span_boost_kernel(
    const float* __restrict__ scores,
    const int*   __restrict__ mask,
    const float* __restrict__ gamma_p,
    const float* __restrict__ wlog,
    float*       __restrict__ out)
{
    __shared__ float    sv[SV_PAD];        // masked values; sv[i] = token col0-LPAD+i
    __shared__ float    sww[NW];
    __shared__ unsigned xb[HALO];          // CTA-left-halo boost (keyed max)
    __shared__ float    tailbuf[TPB][15];  // 14 used; stride 15 = conflict-free

    const float NINF = __int_as_float(0xff800000);
    const int   tid  = threadIdx.x;
    const int   row  = blockIdx.y;
    const int   col0 = blockIdx.x * TILE;
    const float* srow = scores + (size_t)row * N_COLS;
    const int*   mrow = mask   + (size_t)row * N_COLS;
    const int base_g = col0 - LPAD;

    // ---- stage masked tile (vectorized; scalar fallback at row edges) ----
    for (int i = tid * 4; i < SV_PAD; i += TPB * 4) {
        int g = base_g + i;
        float4 v;
        if (g >= 0 && g + 3 < N_COLS) {
            float4 s4 = *reinterpret_cast<const float4*>(srow + g);
            int4   m4 = *reinterpret_cast<const int4*>(mrow + g);
            v.x = (m4.x == 0) ? NEGV : s4.x;
            v.y = (m4.y == 0) ? NEGV : s4.y;
            v.z = (m4.z == 0) ? NEGV : s4.z;
            v.w = (m4.w == 0) ? NEGV : s4.w;
        } else {
            float t[4];
            #pragma unroll
            for (int k = 0; k < 4; k++) {
                int gg = g + k;
                t[k] = (gg >= 0 && gg < N_COLS)
                         ? ((mrow[gg] == 0) ? NEGV : srow[gg]) : NINF;
            }
            v.x = t[0]; v.y = t[1]; v.z = t[2]; v.w = t[3];
        }
        *reinterpret_cast<float4*>(sv + i) = v;
    }
    if (tid < HALO) xb[tid] = KEY_NINF;
    if (tid == 0) {  // softmax over 15 width logits
        float mx = wlog[0];
        #pragma unroll
        for (int j = 1; j < W_MAX; j++) mx = fmaxf(mx, wlog[j]);
        float e[W_MAX], ssum = 0.f;
        #pragma unroll
        for (int j = 0; j < W_MAX; j++) { e[j] = expf(wlog[j] - mx); ssum += e[j]; }
        float inv = 1.f / ssum;
        #pragma unroll
        for (int j = 0; j < NW; j++) sww[j] = e[j + 1] * inv;  // widths 2..15
    }
    __syncthreads();

    float ww[NW];
    #pragma unroll
    for (int j = 0; j < NW; j++) ww[j] = sww[j];

    const int base = LPAD + tid * K_TOK;   // sv index of this thread's token 0
    float r[K_TOK + 2 * HALO - 6];         // r[0..21]
    float boost[K_TOK + HALO];             // tokens 0..21

    // initial r window: r[4..21] (start j=7 needs r[7..21]); 4-aligned chunks
    #pragma unroll
    for (int q = 1; q < 5; q++) {
        float4 f = *reinterpret_cast<const float4*>(&sv[base + 4 * q]);
        r[4*q+0] = f.x; r[4*q+1] = f.y; r[4*q+2] = f.z; r[4*q+3] = f.w;
    }
    {
        float2 f = *reinterpret_cast<const float2*>(&sv[base + 20]);
        r[20] = f.x; r[21] = f.y;
    }

    // ---- own 8 starts, descending; inline-scaled h; streamed retirement ----
    #pragma unroll
    for (int jj = 0; jj < K_TOK; jj++) {
        const int j = K_TOK - 1 - jj;      // 7 .. 0
        if (j == 3) {                      // JIT load of r[0..3]
            float4 f = *reinterpret_cast<const float4*>(&sv[base]);
            r[0] = f.x; r[1] = f.y; r[2] = f.z; r[3] = f.w;
        }

        float h[NW];
        float m = fminf(r[j], r[j + 1]);
        h[0] = ww[0] * m;
        #pragma unroll
        for (int w = 3; w <= W_MAX; w++) {
            m = fminf(m, r[j + w - 1]);
            h[w - 2] = ww[w - 2] * m;
        }

        float g = h[NW - 1];                               // d = 15
        if (j == K_TOK - 1) boost[j + 14] = g;
        else                boost[j + 14] = fmaxf(boost[j + 14], g);
        #pragma unroll
        for (int d = W_MAX - 1; d >= 2; d--) {             // d = 14..2
            g = fmaxf(g, h[d - 2]);
            if (j == K_TOK - 1) boost[j + d - 1] = g;
            else                boost[j + d - 1] = fmaxf(boost[j + d - 1], g);
        }
        boost[j] = g;                                      // d = 1 (first touch)

        if (j >= 1) tailbuf[tid][j + 6] = boost[j + 14];   // retire token j+14
    }
    // retire remaining tail tokens 8..14 (final after j=0)
    #pragma unroll
    for (int k = 0; k < 7; k++) tailbuf[tid][k] = boost[8 + k];

    // ---- CTA-left halo starts: threads 0..13 compute start col0-14+h ----
    if (tid < HALO) {
        const int h0 = tid;                // start at sv index h0 + 2
        float mm[NW];
        float m = fminf(sv[h0 + 2], sv[h0 + 3]);
        mm[0] = ww[0] * m;
        #pragma unroll
        for (int w = 3; w <= W_MAX; w++) {
            m = fminf(m, sv[h0 + 1 + w]);
            mm[w - 2] = ww[w - 2] * m;
        }
        float g = mm[NW - 1];
        atomicMax(&xb[h0], fkey(g));       // d = 15 -> token h0
        #pragma unroll
        for (int d = W_MAX - 1; d >= 2; d--) {
            g = fmaxf(g, mm[d - 2]);
            int i = h0 + d - W_MAX;
            if (i >= 0) atomicMax(&xb[i], fkey(g));
        }
    }
    __syncthreads();

    // ---- merge incoming contributions into own tokens 0..7 ----
    if (tid >= 2) {
        #pragma unroll
        for (int k = 0; k < K_TOK; k++)
            boost[k] = fmaxf(boost[k], tailbuf[tid - 1][k]);
        #pragma unroll
        for (int k = 0; k < 6; k++)
            boost[k] = fmaxf(boost[k], tailbuf[tid - 2][k + 8]);
    } else if (tid == 1) {
        #pragma unroll
        for (int k = 0; k < K_TOK; k++)
            boost[k] = fmaxf(boost[k], tailbuf[0][k]);
        #pragma unroll
        for (int k = 0; k < 6; k++)
            boost[k] = fmaxf(boost[k], funkey(xb[k + 8]));
    } else {
        #pragma unroll
        for (int k = 0; k < K_TOK; k++)
            boost[k] = fmaxf(boost[k], funkey(xb[k]));
    }

    // ---- epilogue: out = score + gamma * max(boost, masked[r]) ----
    const float gamma = *gamma_p;
    const int tcol = col0 + tid * K_TOK;
    float* orow = out + (size_t)row * N_COLS;
    #pragma unroll
    for (int q = 0; q < K_TOK / 4; q++) {
        float4 s4 = *reinterpret_cast<const float4*>(&srow[tcol + 4 * q]);
        float4 o;
        o.x = s4.x + gamma * fmaxf(boost[4*q+0], r[4*q+0]);
        o.y = s4.y + gamma * fmaxf(boost[4*q+1], r[4*q+1]);
        o.z = s4.z + gamma * fmaxf(boost[4*q+2], r[4*q+2]);
        o.w = s4.w + gamma * fmaxf(boost[4*q+3], r[4*q+3]);
        *reinterpret_cast<float4*>(&orow[tcol + 4 * q]) = o;
    }
}

extern "C" void kernel_launch(void* const* d_in, const int* in_sizes, int n_in,
                              void* d_out, int out_size)
{
    const float* scores = (const float*)d_in[0];
    const int*   mask   = (const int*)d_in[1];
    const float* gamma  = (const float*)d_in[2];
    const float* wlog   = (const float*)d_in[3];
    float* out = (float*)d_out;
    const int B = in_sizes[0] / N_COLS;   // 512
    dim3 grid(N_COLS / TILE, B);          // (4, 512)
    span_boost_kernel<<<grid, TPB>>>(scores, mask, gamma, wlog, out);
}